// round 1
// baseline (speedup 1.0000x reference)
#include <cuda_runtime.h>
#include <math.h>

#define BSZ 8
#define NQ  900
#define DD  256
#define KK  10
#define NROWS (BSZ*NQ)          // 7200
#define NFK  (NROWS*KK)         // 72000
#define FDIM 576
#define IOU_THR 0.4f
#define TWO_PI 6.283185307179586f
#define LOG2_10000 13.287712379549449f

// ---------------- scratch (static device globals; no allocations) ----------------
__device__ float g_feats[(size_t)NFK * FDIM];   // 166 MB
__device__ float g_hidden[(size_t)NFK * DD];    // 73.7 MB
__device__ float g_feat4[(size_t)NFK * DD];     // 73.7 MB
__device__ float g_h1[(size_t)NROWS * DD];
__device__ float g_curneg[(size_t)NROWS * DD];
__device__ float g_ct[(size_t)NROWS * DD];
__device__ float g_mk[NFK];
__device__ float g_ioumk[NFK];
__device__ float g_neg[NROWS];
__device__ int   g_idx[NFK];

// ---------------- kernel 1: top-K selection + masks ----------------
__global__ void topk_kernel(const float* __restrict__ ious,
                            const float* __restrict__ gmask,
                            int* __restrict__ idx, float* __restrict__ mk,
                            float* __restrict__ ioumk, float* __restrict__ negv)
{
    int row = blockIdx.x * blockDim.x + threadIdx.x;
    if (row >= NROWS) return;
    int b = row / NQ;
    float negi = 1.0f - gmask[row];
    negv[row] = negi;

    float tv[KK];
    int   ti[KK];
#pragma unroll
    for (int q = 0; q < KK; q++) { tv[q] = -1.0f; ti[q] = 0; }

    if (negi != 0.0f) {
        const float* R  = ious + (size_t)row * NQ;
        const float* Mm = gmask + (size_t)b * NQ;
        for (int j = 0; j < NQ; j++) {
            float v = R[j] * Mm[j];
            if (v > tv[KK - 1]) {           // strict: stable vs argsort ties
                int p = KK - 1;
                while (p > 0 && v > tv[p - 1]) {
                    tv[p] = tv[p - 1]; ti[p] = ti[p - 1]; p--;
                }
                tv[p] = v; ti[p] = j;
            }
        }
    }
#pragma unroll
    for (int q = 0; q < KK; q++) {
        float v = tv[q] < 0.0f ? 0.0f : tv[q];
        float nm = (negi != 0.0f) ? gmask[(size_t)b * NQ + ti[q]] : 0.0f;
        float m = nm * (v >= IOU_THR ? 1.0f : 0.0f);
        mk[row * KK + q] = m;
        ioumk[row * KK + q] = v * m;
        idx[row * KK + q] = ti[q];
    }
}

// ---------------- kernel 2: build feature rows [NFK, 576] ----------------
__global__ void features_kernel(const float* __restrict__ bboxes,
                                const int* __restrict__ idx,
                                const float* __restrict__ mk,
                                const float* __restrict__ ioumk,
                                float* __restrict__ feats)
{
    int r = blockIdx.x;                 // 0..NFK-1
    int t = threadIdx.x;                // 0..127
    float m = mk[r];
    float* out = feats + (size_t)r * FDIM;
    if (m == 0.0f) {
        for (int q = t; q < FDIM; q += 128) out[q] = 0.0f;
        return;
    }
    int row = r / KK;
    int b = row / NQ, i = row % NQ;
    int j = idx[r];
    const float* bi = bboxes + ((size_t)b * NQ + i) * 4;
    const float* bj = bboxes + ((size_t)b * NQ + j) * 4;
    float dcx = 0.5f * (bj[0] + bj[2]) - 0.5f * (bi[0] + bi[2]);
    float dcy = 0.5f * (bj[1] + bj[3]) - 0.5f * (bi[1] + bi[3]);
    float dw  = (bj[2] - bj[0]) - (bi[2] - bi[0]);
    float dh  = (bj[3] - bj[1]) - (bi[3] - bi[1]);
    float p0 = logf(fmaxf(fabsf(dcx), 1e-7f));
    float p1 = logf(fmaxf(fabsf(dcy), 1e-7f));
    float p2 = logf(fmaxf(fabsf(dw),  1e-7f));
    float p3 = logf(fmaxf(fabsf(dh),  1e-7f));

    if (t < 64) out[t] = ioumk[r];

    int p = t >> 1;
    float inv_dim = exp2f(-((2.0f * (float)p) / 128.0f) * LOG2_10000);
    float s = TWO_PI * inv_dim;
    out[64 + t]       = sinf(p0 * s) * m;
    out[64 + 128 + t] = cosf(p1 * s) * m;
    out[64 + 256 + t] = sinf(p2 * s) * m;
    out[64 + 384 + t] = cosf(p3 * s) * m;
}

// ---------------- tiled SGEMM: C = epilogue(A[M,K] @ B[K,N] + bias) ----------------
// epilogue: optional relu, optional per-row scale. K % 16 == 0, N % 64 == 0.
#define BM 64
#define BN 64
#define BK 16
__global__ __launch_bounds__(256) void sgemm_kernel(
    const float* __restrict__ A, const float* __restrict__ B,
    const float* __restrict__ bias, float* __restrict__ C,
    int M, int K, int N, int relu, const float* __restrict__ rowscale)
{
    __shared__ float As[BK][BM];
    __shared__ float Bs[BK][BN];
    int tid = threadIdx.x;
    int bm = blockIdx.y * BM;
    int bn = blockIdx.x * BN;
    int ty = tid >> 4;          // 0..15
    int tx = tid & 15;          // 0..15
    int ar = tid >> 2;          // 0..63
    int ac = (tid & 3) * 4;     // 0,4,8,12
    int br = tid >> 4;          // 0..15
    int bc = (tid & 15) * 4;    // 0..60

    float acc[4][4];
#pragma unroll
    for (int i = 0; i < 4; i++)
#pragma unroll
        for (int jj = 0; jj < 4; jj++) acc[i][jj] = 0.0f;

    for (int k0 = 0; k0 < K; k0 += BK) {
        float4 av = make_float4(0.f, 0.f, 0.f, 0.f);
        if (bm + ar < M)
            av = *(const float4*)(A + (size_t)(bm + ar) * K + k0 + ac);
        As[ac + 0][ar] = av.x; As[ac + 1][ar] = av.y;
        As[ac + 2][ar] = av.z; As[ac + 3][ar] = av.w;
        float4 bv = *(const float4*)(B + (size_t)(k0 + br) * N + bn + bc);
        *(float4*)(&Bs[br][bc]) = bv;
        __syncthreads();
#pragma unroll
        for (int kk = 0; kk < BK; kk++) {
            float4 a4 = *(const float4*)(&As[kk][ty * 4]);
            float4 b4 = *(const float4*)(&Bs[kk][tx * 4]);
            float avv[4] = {a4.x, a4.y, a4.z, a4.w};
            float bvv[4] = {b4.x, b4.y, b4.z, b4.w};
#pragma unroll
            for (int i = 0; i < 4; i++)
#pragma unroll
                for (int jj = 0; jj < 4; jj++)
                    acc[i][jj] += avv[i] * bvv[jj];
        }
        __syncthreads();
    }
#pragma unroll
    for (int i = 0; i < 4; i++) {
        int row = bm + ty * 4 + i;
        if (row >= M) continue;
        float rs = rowscale ? rowscale[row] : 1.0f;
#pragma unroll
        for (int jj = 0; jj < 4; jj++) {
            int col = bn + tx * 4 + jj;
            float v = acc[i][jj] + bias[col];
            if (relu) v = fmaxf(v, 0.0f);
            v *= rs;
            C[(size_t)row * N + col] = v;
        }
    }
}

// ---------------- masked max over K + add cur*neg ----------------
__global__ void agg_kernel(const float* __restrict__ feat4,
                           const float* __restrict__ curneg,
                           float* __restrict__ ct)
{
    int row = blockIdx.x;
    int c = threadIdx.x;
    const float* p = feat4 + ((size_t)row * KK) * DD + c;
    float mx = p[0];
#pragma unroll
    for (int k = 1; k < KK; k++) mx = fmaxf(mx, p[(size_t)k * DD]);
    ct[(size_t)row * DD + c] = curneg[(size_t)row * DD + c] + mx;
}

// ---------------- launch ----------------
extern "C" void kernel_launch(void* const* d_in, const int* in_sizes, int n_in,
                              void* d_out, int out_size)
{
    const float* tgt    = (const float*)d_in[0];
    const float* ious   = (const float*)d_in[1];
    const float* bboxes = (const float*)d_in[2];
    const float* gmask  = (const float*)d_in[3];
    const float* W1 = (const float*)d_in[4];
    const float* b1 = (const float*)d_in[5];
    const float* W2 = (const float*)d_in[6];
    const float* b2 = (const float*)d_in[7];
    const float* W3 = (const float*)d_in[8];
    const float* b3 = (const float*)d_in[9];
    const float* W4 = (const float*)d_in[10];
    const float* b4 = (const float*)d_in[11];
    const float* W5 = (const float*)d_in[12];
    const float* b5 = (const float*)d_in[13];
    float* out = (float*)d_out;

    float *feats, *hidden, *feat4, *h1, *curneg, *ct, *mk, *ioumk, *negv;
    int* idx;
    cudaGetSymbolAddress((void**)&feats,  g_feats);
    cudaGetSymbolAddress((void**)&hidden, g_hidden);
    cudaGetSymbolAddress((void**)&feat4,  g_feat4);
    cudaGetSymbolAddress((void**)&h1,     g_h1);
    cudaGetSymbolAddress((void**)&curneg, g_curneg);
    cudaGetSymbolAddress((void**)&ct,     g_ct);
    cudaGetSymbolAddress((void**)&mk,     g_mk);
    cudaGetSymbolAddress((void**)&ioumk,  g_ioumk);
    cudaGetSymbolAddress((void**)&negv,   g_neg);
    cudaGetSymbolAddress((void**)&idx,    g_idx);

    // 1) top-K + masks
    topk_kernel<<<(NROWS + 127) / 128, 128>>>(ious, gmask, idx, mk, ioumk, negv);

    // 2) feature rows
    features_kernel<<<NFK, 128>>>(bboxes, idx, mk, ioumk, feats);

    // 3) cur = relu(tgt@W1+b1)@W2+b2, fused *neg
    {
        dim3 g(DD / BN, (NROWS + BM - 1) / BM);
        sgemm_kernel<<<g, 256>>>(tgt, W1, b1, h1, NROWS, DD, DD, 1, nullptr);
        sgemm_kernel<<<g, 256>>>(h1, W2, b2, curneg, NROWS, DD, DD, 0, negv);
    }

    // 4) hidden = relu(features@W3+b3); feat4 = (hidden@W4+b4)*mk
    {
        dim3 g(DD / BN, (NFK + BM - 1) / BM);
        sgemm_kernel<<<g, 256>>>(feats, W3, b3, hidden, NFK, FDIM, DD, 1, nullptr);
        sgemm_kernel<<<g, 256>>>(hidden, W4, b4, feat4, NFK, DD, DD, 0, mk);
    }

    // 5) ct = cur*neg + max_k feat4
    agg_kernel<<<NROWS, DD>>>(feat4, curneg, ct);

    // 6) out = relu(ct@W5+b5)*neg
    {
        dim3 g(DD / BN, (NROWS + BM - 1) / BM);
        sgemm_kernel<<<g, 256>>>(ct, W5, b5, out, NROWS, DD, DD, 1, negv);
    }
}

// round 16
// speedup vs baseline: 1.4245x; 1.4245x over previous
#include <cuda_runtime.h>
#include <math.h>

#define BSZ 8
#define NQ  900
#define DD  256
#define KK  10
#define NROWS (BSZ*NQ)          // 7200
#define NFK  (NROWS*KK)         // 72000
#define FDIM 576
#define IOU_THR 0.4f
#define TWO_PI 6.283185307179586f
#define LOG2_10000 13.287712379549449f

// ---------------- scratch (static device globals; no allocations) ----------------
__device__ float g_feats[(size_t)NFK * FDIM];   // compacted feature rows
__device__ float g_hidden[(size_t)NFK * DD];    // compacted
__device__ float g_feat4[(size_t)NFK * DD];     // compacted
__device__ float g_h1[(size_t)NROWS * DD];
__device__ float g_curneg[(size_t)NROWS * DD];
__device__ float g_ct[(size_t)NROWS * DD];
__device__ float g_mk[NFK];
__device__ float g_ioumk[NFK];
__device__ float g_neg[NROWS];
__device__ int   g_idx[NFK];
__device__ int   g_list[NFK];   // compacted c -> original r
__device__ int   g_pos[NFK];    // original r -> compacted c, or -1
__device__ int   g_count;

__global__ void zero_counter_kernel() { g_count = 0; }

// ---------------- kernel 1: top-K selection + masks ----------------
__global__ void topk_kernel(const float* __restrict__ ious,
                            const float* __restrict__ gmask)
{
    int row = blockIdx.x * blockDim.x + threadIdx.x;
    if (row >= NROWS) return;
    int b = row / NQ;
    float negi = 1.0f - gmask[row];
    g_neg[row] = negi;

    float tv[KK];
    int   ti[KK];
#pragma unroll
    for (int q = 0; q < KK; q++) { tv[q] = -1.0f; ti[q] = 0; }

    if (negi != 0.0f) {
        const float* R  = ious + (size_t)row * NQ;
        const float* Mm = gmask + (size_t)b * NQ;
        for (int j = 0; j < NQ; j++) {
            float v = R[j] * Mm[j];
            if (v > tv[KK - 1]) {           // strict: stable vs argsort ties
                int p = KK - 1;
                while (p > 0 && v > tv[p - 1]) {
                    tv[p] = tv[p - 1]; ti[p] = ti[p - 1]; p--;
                }
                tv[p] = v; ti[p] = j;
            }
        }
    }
#pragma unroll
    for (int q = 0; q < KK; q++) {
        float v = tv[q] < 0.0f ? 0.0f : tv[q];
        float nm = (negi != 0.0f) ? gmask[(size_t)b * NQ + ti[q]] : 0.0f;
        float m = nm * (v >= IOU_THR ? 1.0f : 0.0f);
        g_mk[row * KK + q] = m;
        g_ioumk[row * KK + q] = v * m;
        g_idx[row * KK + q] = ti[q];
    }
}

// ---------------- kernel 1b: compact active rows ----------------
__global__ void compact_kernel()
{
    int r = blockIdx.x * blockDim.x + threadIdx.x;
    if (r >= NFK) return;
    if (g_mk[r] != 0.0f) {
        int p = atomicAdd(&g_count, 1);
        g_list[p] = r;
        g_pos[r] = p;
    } else {
        g_pos[r] = -1;
    }
}

// ---------------- kernel 2: build compacted feature rows [count, 576] ----------------
__global__ void features_kernel(const float* __restrict__ bboxes)
{
    int t = threadIdx.x;                // 0..127
    int cnt = g_count;
    for (int c = blockIdx.x; c < cnt; c += gridDim.x) {
        int r = g_list[c];
        float* out = g_feats + (size_t)c * FDIM;
        int row = r / KK;
        int b = row / NQ, i = row % NQ;
        int j = g_idx[r];
        const float* bi = bboxes + ((size_t)b * NQ + i) * 4;
        const float* bj = bboxes + ((size_t)b * NQ + j) * 4;
        float dcx = 0.5f * (bj[0] + bj[2]) - 0.5f * (bi[0] + bi[2]);
        float dcy = 0.5f * (bj[1] + bj[3]) - 0.5f * (bi[1] + bi[3]);
        float dw  = (bj[2] - bj[0]) - (bi[2] - bi[0]);
        float dh  = (bj[3] - bj[1]) - (bi[3] - bi[1]);
        float p0 = logf(fmaxf(fabsf(dcx), 1e-7f));
        float p1 = logf(fmaxf(fabsf(dcy), 1e-7f));
        float p2 = logf(fmaxf(fabsf(dw),  1e-7f));
        float p3 = logf(fmaxf(fabsf(dh),  1e-7f));

        if (t < 64) out[t] = g_ioumk[r];

        int p = t >> 1;
        float inv_dim = exp2f(-((2.0f * (float)p) / 128.0f) * LOG2_10000);
        float s = TWO_PI * inv_dim;
        out[64 + t]       = sinf(p0 * s);   // mk == 1 on compacted rows
        out[64 + 128 + t] = cosf(p1 * s);
        out[64 + 256 + t] = sinf(p2 * s);
        out[64 + 384 + t] = cosf(p3 * s);
    }
}

// ---------------- 128x128x8 double-buffered SGEMM ----------------
// C[M,N] = epi(A[M,K] @ B[K,N] + bias); optional relu; optional per-row scale.
// M may be dynamic via Mptr (device count). K % 8 == 0.
#define TBM 128
#define TBN 128
#define TBK 8
__global__ __launch_bounds__(256, 2) void sgemm128_kernel(
    const float* __restrict__ A, const float* __restrict__ B,
    const float* __restrict__ bias, float* __restrict__ C,
    int Mfixed, const int* __restrict__ Mptr, int K, int N,
    int relu, const float* __restrict__ rowscale)
{
    int M = Mptr ? *Mptr : Mfixed;
    int bm = blockIdx.y * TBM;
    if (bm >= M) return;
    int bn = blockIdx.x * TBN;

    __shared__ float As[2][TBK][TBM];
    __shared__ float Bs[2][TBK][TBN];

    int tid = threadIdx.x;
    // A loader: one float4 per thread
    int ar = tid >> 1;              // 0..127
    int ac = (tid & 1) * 4;         // 0 or 4
    // B loader: one float4 per thread
    int br = tid >> 5;              // 0..7
    int bc = (tid & 31) * 4;        // 0..124
    // compute mapping
    int tx = tid & 15;              // 0..15 -> 8 cols each
    int ty = tid >> 4;              // 0..15 -> 8 rows each

    const float* Arow = A + (size_t)(bm + ar) * K + ac;
    bool arow_ok = (bm + ar) < M;

    float acc[8][8];
#pragma unroll
    for (int i = 0; i < 8; i++)
#pragma unroll
        for (int jj = 0; jj < 8; jj++) acc[i][jj] = 0.0f;

    // load tile 0
    {
        float4 av = arow_ok ? *(const float4*)(Arow)
                            : make_float4(0.f, 0.f, 0.f, 0.f);
        As[0][ac + 0][ar] = av.x; As[0][ac + 1][ar] = av.y;
        As[0][ac + 2][ar] = av.z; As[0][ac + 3][ar] = av.w;
        float4 bv = *(const float4*)(B + (size_t)br * N + bn + bc);
        *(float4*)(&Bs[0][br][bc]) = bv;
    }
    __syncthreads();

    int nt = K / TBK;
    int buf = 0;
    for (int it = 0; it < nt; it++) {
        float4 av, bv;
        bool has_next = (it + 1) < nt;
        if (has_next) {
            int k0 = (it + 1) * TBK;
            av = arow_ok ? *(const float4*)(Arow + k0)
                         : make_float4(0.f, 0.f, 0.f, 0.f);
            bv = *(const float4*)(B + (size_t)(k0 + br) * N + bn + bc);
        }
#pragma unroll
        for (int kk = 0; kk < TBK; kk++) {
            float4 a0 = *(const float4*)(&As[buf][kk][ty * 8]);
            float4 a1 = *(const float4*)(&As[buf][kk][ty * 8 + 4]);
            float4 b0 = *(const float4*)(&Bs[buf][kk][tx * 8]);
            float4 b1 = *(const float4*)(&Bs[buf][kk][tx * 8 + 4]);
            float af[8] = {a0.x, a0.y, a0.z, a0.w, a1.x, a1.y, a1.z, a1.w};
            float bf[8] = {b0.x, b0.y, b0.z, b0.w, b1.x, b1.y, b1.z, b1.w};
#pragma unroll
            for (int i = 0; i < 8; i++)
#pragma unroll
                for (int jj = 0; jj < 8; jj++)
                    acc[i][jj] += af[i] * bf[jj];
        }
        if (has_next) {
            int nb = buf ^ 1;
            As[nb][ac + 0][ar] = av.x; As[nb][ac + 1][ar] = av.y;
            As[nb][ac + 2][ar] = av.z; As[nb][ac + 3][ar] = av.w;
            *(float4*)(&Bs[nb][br][bc]) = bv;
            __syncthreads();
            buf = nb;
        }
    }

#pragma unroll
    for (int i = 0; i < 8; i++) {
        int row = bm + ty * 8 + i;
        if (row >= M) continue;
        float rs = rowscale ? rowscale[row] : 1.0f;
#pragma unroll
        for (int jj = 0; jj < 8; jj++) {
            int col = bn + tx * 8 + jj;
            float v = acc[i][jj] + bias[col];
            if (relu) v = fmaxf(v, 0.0f);
            v *= rs;
            C[(size_t)row * N + col] = v;
        }
    }
}

// ---------------- masked max over K (via pos map) + add cur*neg ----------------
__global__ void agg_kernel()
{
    int row = blockIdx.x;
    int c = threadIdx.x;
    const int* pp = g_pos + row * KK;
    float mx = -1e30f;
#pragma unroll
    for (int k = 0; k < KK; k++) {
        int q = pp[k];
        float v = (q >= 0) ? g_feat4[(size_t)q * DD + c] : 0.0f;
        mx = fmaxf(mx, v);
    }
    g_ct[(size_t)row * DD + c] = g_curneg[(size_t)row * DD + c] + mx;
}

// ---------------- launch ----------------
extern "C" void kernel_launch(void* const* d_in, const int* in_sizes, int n_in,
                              void* d_out, int out_size)
{
    const float* tgt    = (const float*)d_in[0];
    const float* ious   = (const float*)d_in[1];
    const float* bboxes = (const float*)d_in[2];
    const float* gmask  = (const float*)d_in[3];
    const float* W1 = (const float*)d_in[4];
    const float* b1 = (const float*)d_in[5];
    const float* W2 = (const float*)d_in[6];
    const float* b2 = (const float*)d_in[7];
    const float* W3 = (const float*)d_in[8];
    const float* b3 = (const float*)d_in[9];
    const float* W4 = (const float*)d_in[10];
    const float* b4 = (const float*)d_in[11];
    const float* W5 = (const float*)d_in[12];
    const float* b5 = (const float*)d_in[13];
    float* out = (float*)d_out;

    float *feats, *hidden, *feat4, *h1, *curneg, *ct, *negv;
    int* countp;
    cudaGetSymbolAddress((void**)&feats,  g_feats);
    cudaGetSymbolAddress((void**)&hidden, g_hidden);
    cudaGetSymbolAddress((void**)&feat4,  g_feat4);
    cudaGetSymbolAddress((void**)&h1,     g_h1);
    cudaGetSymbolAddress((void**)&curneg, g_curneg);
    cudaGetSymbolAddress((void**)&ct,     g_ct);
    cudaGetSymbolAddress((void**)&negv,   g_neg);
    cudaGetSymbolAddress((void**)&countp, g_count);

    // 1) top-K + masks, compaction
    zero_counter_kernel<<<1, 1>>>();
    topk_kernel<<<(NROWS + 127) / 128, 128>>>(ious, gmask);
    compact_kernel<<<(NFK + 255) / 256, 256>>>();

    // 2) compacted feature rows
    features_kernel<<<2048, 128>>>(bboxes);

    // 3) cur = relu(tgt@W1+b1)@W2+b2, fused *neg
    {
        dim3 g(DD / TBN, (NROWS + TBM - 1) / TBM);
        sgemm128_kernel<<<g, 256>>>(tgt, W1, b1, h1, NROWS, nullptr, DD, DD, 1, nullptr);
        sgemm128_kernel<<<g, 256>>>(h1, W2, b2, curneg, NROWS, nullptr, DD, DD, 0, negv);
    }

    // 4) hidden = relu(featsC@W3+b3); feat4C = hiddenC@W4+b4   (mk==1 on compacted rows)
    {
        dim3 g(DD / TBN, (NFK + TBM - 1) / TBM);   // worst-case grid; blocks early-exit on count
        sgemm128_kernel<<<g, 256>>>(feats, W3, b3, hidden, 0, countp, FDIM, DD, 1, nullptr);
        sgemm128_kernel<<<g, 256>>>(hidden, W4, b4, feat4, 0, countp, DD, DD, 0, nullptr);
    }

    // 5) ct = cur*neg + max_k (feat4*mk)
    agg_kernel<<<NROWS, DD>>>();

    // 6) out = relu(ct@W5+b5)*neg
    {
        dim3 g(DD / TBN, (NROWS + TBM - 1) / TBM);
        sgemm128_kernel<<<g, 256>>>(ct, W5, b5, out, NROWS, nullptr, DD, DD, 1, negv);
    }
}